// round 7
// baseline (speedup 1.0000x reference)
#include <cuda_runtime.h>
#include <cuda_bf16.h>
#include <math.h>

#define Bb 2
#define Nn 286
#define HH 150
#define TE 8            // edges per tile
#define MAXE 82944      // >= B*N*(N+1)/2 = 82082

// ---------------- device scratch (no allocations allowed) ----------------
// NOTE: these symbols must ONLY be referenced from device code. Referencing
// them in host code binds the host shadow variable (silent corruption on
// GB300 because ATS makes host addresses GPU-dereferenceable).
__device__ int   g_edge_count;
__device__ int   g_packed[MAXE];  // (b<<20)|(i<<10)|j
__device__ float g_dist[MAXE];
__device__ float g_f0[Bb*Nn*4];
__device__ float g_f1[Bb*Nn*8];
__device__ float g_f2[Bb*Nn*8];
__device__ float g_f3[Bb*Nn*8];
// per-edge radial kernels (scratch; L2-resident at typical edge counts)
__device__ float g_K0[MAXE*32];
__device__ float g_K1[MAXE*64];
__device__ float g_K2[MAXE*64];

__device__ __forceinline__ float sp_act(float x) {
    // softplus(5x)/5
    float t = 5.0f * x;
    if (t > 15.0f) return x;
    return 0.2f * __logf(1.0f + __expf(t));
}

// ---- packed fp32x2 FMA helpers (bit-exact 2x FFMA through one instr) ----
__device__ __forceinline__ void ffma2(unsigned long long &d,
                                      unsigned long long a,
                                      unsigned long long b) {
    asm("fma.rn.f32x2 %0, %1, %2, %0;" : "+l"(d) : "l"(a), "l"(b));
}
__device__ __forceinline__ unsigned long long bcast2(float w) {
    unsigned long long r;
    asm("mov.b64 %0, {%1, %1};" : "=l"(r) : "f"(w));
    return r;
}
__device__ __forceinline__ float2 unpk(unsigned long long a) {
    float lo, hi;
    asm("mov.b64 {%0, %1}, %2;" : "=f"(lo), "=f"(hi) : "l"(a));
    return make_float2(lo, hi);
}

// ---------------- init: zero accumulators, embed features ----------------
__global__ void init_kernel(const int* __restrict__ Z, const float* __restrict__ emb) {
    int t = blockIdx.x * blockDim.x + threadIdx.x;
    if (t == 0) g_edge_count = 0;
    if (t < Bb*Nn*8) { g_f1[t] = 0.f; g_f2[t] = 0.f; g_f3[t] = 0.f; }
    if (t < Bb*Nn*4) {
        int n = t >> 2, c = t & 3;
        g_f0[t] = emb[Z[n]*4 + c];
    }
}

// ---------------- build compacted unordered-pair list ----------------
__global__ void build_edges(const float* __restrict__ xyz) {
    int t = blockIdx.x * blockDim.x + threadIdx.x;
    if (t >= Bb*Nn*Nn) return;
    int b = t / (Nn*Nn);
    int r = t % (Nn*Nn);
    int i = r / Nn, j = r % Nn;
    if (j < i) return;                      // unordered pairs + self
    const float* pi = xyz + (b*Nn + i)*3;
    const float* pj = xyz + (b*Nn + j)*3;
    float dx = pi[0]-pj[0], dy = pi[1]-pj[1], dz = pi[2]-pj[2];
    float d = sqrtf(dx*dx + dy*dy + dz*dz + 1e-12f);
    if (d <= 3.0f) {
        int idx = atomicAdd(&g_edge_count, 1);
        g_packed[idx] = (b << 20) | (i << 10) | j;
        g_dist[idx]   = d;
    }
}

// ---------------- hidden 150x150 layer over an 8-edge tile (f32x2) --------
__device__ __forceinline__ void hidden_layer(const float* __restrict__ src,
                                             float* __restrict__ dst,
                                             const float* __restrict__ W, int tid) {
    if (tid < HH) {
        unsigned long long acc0 = 0, acc1 = 0, acc2 = 0, acc3 = 0;
        const float* wc = W + tid;
        #pragma unroll 1
        for (int kk = 0; kk < HH; kk += 6) {
            float w[6];
            #pragma unroll
            for (int u = 0; u < 6; u++) w[u] = __ldg(wc + (kk + u)*HH);
            #pragma unroll
            for (int u = 0; u < 6; u++) {
                unsigned long long wd = bcast2(w[u]);
                const ulonglong2* hr = reinterpret_cast<const ulonglong2*>(src + (kk + u)*TE);
                ulonglong2 p0 = hr[0], p1 = hr[1];
                ffma2(acc0, p0.x, wd); ffma2(acc1, p0.y, wd);
                ffma2(acc2, p1.x, wd); ffma2(acc3, p1.y, wd);
            }
        }
        const float S = 0.0816496580927726f;   // 1/sqrt(150)
        float2 a0 = unpk(acc0), a1 = unpk(acc1), a2 = unpk(acc2), a3 = unpk(acc3);
        float4 o0, o1;
        o0.x = sp_act(a0.x*S); o0.y = sp_act(a0.y*S);
        o0.z = sp_act(a1.x*S); o0.w = sp_act(a1.y*S);
        o1.x = sp_act(a2.x*S); o1.y = sp_act(a2.y*S);
        o1.z = sp_act(a3.x*S); o1.w = sp_act(a3.y*S);
        float4* dr = reinterpret_cast<float4*>(dst + tid*TE);
        dr[0] = o0; dr[1] = o1;
    }
}

// ---------------- output layer: 150 -> DIO per edge (f32x2) ----------------
template<int DIO>
__device__ __forceinline__ void out_layer(const float* __restrict__ HA,
                                          const float* __restrict__ wo,
                                          float* __restrict__ Kout, int tid) {
    constexpr int GROUPS = 128 / DIO;       // 4 (DIO=32) or 2 (DIO=64)
    constexpr int EPG    = TE / GROUPS;     // 2 or 4
    constexpr int NP     = EPG / 2;         // 1 or 2 packed accumulators
    if (tid >= 128) return;
    int o  = tid % DIO;
    int eg = tid / DIO;
    unsigned long long acc[NP];
    #pragma unroll
    for (int q = 0; q < NP; q++) acc[q] = 0ULL;
    const float* wc = wo + o;
    #pragma unroll 1
    for (int kk = 0; kk < HH; kk += 6) {
        float w[6];
        #pragma unroll
        for (int u = 0; u < 6; u++) w[u] = __ldg(wc + (kk + u)*DIO);
        #pragma unroll
        for (int u = 0; u < 6; u++) {
            unsigned long long wd = bcast2(w[u]);
            const unsigned long long* hr =
                reinterpret_cast<const unsigned long long*>(HA + (kk + u)*TE + eg*EPG);
            #pragma unroll
            for (int q = 0; q < NP; q++) ffma2(acc[q], hr[q], wd);
        }
    }
    #pragma unroll
    for (int q = 0; q < NP; q++) {
        float2 v = unpk(acc[q]);
        Kout[(eg*EPG + 2*q    )*DIO + o] = v.x;
        Kout[(eg*EPG + 2*q + 1)*DIO + o] = v.y;
    }
}

// ---------------- radial MLP for all 3 convs (independent work items) ------
__global__ __launch_bounds__(160)
void radial_kernel(const float* __restrict__ c0w1, const float* __restrict__ c0w2,
                   const float* __restrict__ c0w3, const float* __restrict__ c0wo,
                   const float* __restrict__ c1w1, const float* __restrict__ c1w2,
                   const float* __restrict__ c1w3, const float* __restrict__ c1wo,
                   const float* __restrict__ c2w1, const float* __restrict__ c2w2,
                   const float* __restrict__ c2w3, const float* __restrict__ c2wo) {
    __shared__ __align__(16) float HA[HH*TE];
    __shared__ __align__(16) float HB[HH*TE];
    __shared__ float sb0[TE], sb1[TE], sb2[TE];

    const int tid = threadIdx.x;
    const int cnt = g_edge_count;
    const int ntiles = (cnt + TE - 1) / TE;
    const int total = 3 * ntiles;
    const float INV_SQRT3 = 0.5773502691896258f;
    const float PI_2 = 1.5707963267948966f;

    for (int work = blockIdx.x; work < total; work += gridDim.x) {
        int layer = work % 3;
        int tile  = work / 3;
        const float *w1, *w2, *w3, *wo;
        if (layer == 0)      { w1 = c0w1; w2 = c0w2; w3 = c0w3; wo = c0wo; }
        else if (layer == 1) { w1 = c1w1; w2 = c1w2; w3 = c1w3; wo = c1wo; }
        else                 { w1 = c2w1; w2 = c2w2; w3 = c2w3; wo = c2wo; }

        // stage basis
        if (tid < TE) {
            int idx = tile*TE + tid;
            float d = (idx < cnt) ? g_dist[idx] : 1e9f;
            float x0 = d * (1.0f/1.5f);
            float x1 = x0 - 1.0f;
            float x2 = x0 - 2.0f;
            float c0 = cosf(PI_2*x0), c1 = cosf(PI_2*x1), c2 = cosf(PI_2*x2);
            sb0[tid] = (fabsf(x0) < 1.f) ? c0*c0 : 0.f;
            sb1[tid] = (fabsf(x1) < 1.f) ? c1*c1 : 0.f;
            sb2[tid] = (fabsf(x2) < 1.f) ? c2*c2 : 0.f;
        }
        __syncthreads();

        // layer 1: basis(3) -> 150
        if (tid < HH) {
            float wa = w1[tid]        * INV_SQRT3;
            float wb = w1[HH + tid]   * INV_SQRT3;
            float wc = w1[2*HH + tid] * INV_SQRT3;
            #pragma unroll
            for (int e = 0; e < TE; e++)
                HA[tid*TE + e] = sp_act(fmaf(sb0[e], wa, fmaf(sb1[e], wb, sb2[e]*wc)));
        }
        __syncthreads();
        hidden_layer(HA, HB, w2, tid);
        __syncthreads();
        hidden_layer(HB, HA, w3, tid);
        __syncthreads();

        if (layer == 0)      out_layer<32>(HA, wo, g_K0 + tile*TE*32, tid);
        else if (layer == 1) out_layer<64>(HA, wo, g_K1 + tile*TE*64, tid);
        else                 out_layer<64>(HA, wo, g_K2 + tile*TE*64, tid);
        __syncthreads();
    }
}

// ---------------- scatter: out[b,i] += K(e) @ f[b,j] (both directions) -----
// LAYER selects the g_* arrays INSIDE device code (host must not touch them).
template<int LAYER>
__global__ void scatter_kernel() {
    constexpr int DIN  = (LAYER == 0) ? 4 : 8;
    constexpr int DOUT = 8;
    const float* __restrict__ K   = (LAYER == 0) ? g_K0 : (LAYER == 1 ? g_K1 : g_K2);
    const float* __restrict__ fin = (LAYER == 0) ? g_f0 : (LAYER == 1 ? g_f1 : g_f2);
    float*       __restrict__ fout= (LAYER == 0) ? g_f1 : (LAYER == 1 ? g_f2 : g_f3);

    const int cnt = g_edge_count;
    const int total = cnt * DOUT;
    const float scale = rsqrtf(150.0f * (float)DIN);
    for (int t = blockIdx.x*blockDim.x + threadIdx.x; t < total;
         t += gridDim.x*blockDim.x) {
        int e = t / DOUT, a = t % DOUT;
        int p = g_packed[e];
        int b = p >> 20, i = (p >> 10) & 1023, j = p & 1023;
        const float* krow = K + e*(DIN*DOUT) + a*DIN;
        const float* fj = fin + (b*Nn + j)*DIN;
        const float* fi = fin + (b*Nn + i)*DIN;
        float s1 = 0.f, s2 = 0.f;
        #pragma unroll
        for (int ji = 0; ji < DIN; ji++) {
            float w = krow[ji];
            s1 = fmaf(w, fj[ji], s1);
            s2 = fmaf(w, fi[ji], s2);
        }
        atomicAdd(&fout[(b*Nn + i)*DOUT + a], s1 * scale);
        if (i != j) atomicAdd(&fout[(b*Nn + j)*DOUT + a], s2 * scale);
    }
}

// ---------------- epilogue: lp-pool, linear, batchnorm, leaky relu ----------
__global__ void final_kernel(const float* __restrict__ lin_w, const float* __restrict__ lin_b,
                             const float* __restrict__ bn_g,  const float* __restrict__ bn_b,
                             float* __restrict__ out) {
    __shared__ float pooled[2][24];
    __shared__ float yv[2][24];
    int t = threadIdx.x;
    if (t < 48) {
        int b = t / 24, c = t % 24;
        const float* src; int cc;
        if      (c < 8)  { src = g_f1; cc = c;      }
        else if (c < 16) { src = g_f2; cc = c - 8;  }
        else             { src = g_f3; cc = c - 16; }
        float s = 0.f;
        for (int n = 0; n < Nn; n++) {
            float v = src[(b*Nn + n)*8 + cc];
            s = fmaf(v, v, s);
        }
        pooled[b][c] = sqrtf(s + 1e-12f);
    }
    __syncthreads();
    if (t < 48) {
        int b = t / 24, o = t % 24;
        float s = lin_b[o];
        for (int c = 0; c < 24; c++) s = fmaf(pooled[b][c], lin_w[o*24 + c], s);
        yv[b][o] = s;
    }
    __syncthreads();
    if (t < 24) {
        float y0 = yv[0][t], y1 = yv[1][t];
        float m   = 0.5f * (y0 + y1);
        float d0  = y0 - m, d1 = y1 - m;
        float var = 0.5f * (d0*d0 + d1*d1);
        float inv = 1.0f / sqrtf(var + 1e-5f);
        #pragma unroll
        for (int b = 0; b < 2; b++) {
            float v = (yv[b][t] - m) * inv * bn_g[t] + bn_b[t];
            out[b*24 + t] = (v > 0.f) ? v : 0.2f * v;
        }
    }
}

// ---------------- launch ----------------
extern "C" void kernel_launch(void* const* d_in, const int* in_sizes, int n_in,
                              void* d_out, int out_size) {
    const float* xyz   = (const float*)d_in[0];
    const int*   Z     = (const int*)  d_in[1];
    const float* emb   = (const float*)d_in[2];
    const float* c0w1  = (const float*)d_in[3];
    const float* c0w2  = (const float*)d_in[4];
    const float* c0w3  = (const float*)d_in[5];
    const float* c0wo  = (const float*)d_in[6];
    const float* c1w1  = (const float*)d_in[7];
    const float* c1w2  = (const float*)d_in[8];
    const float* c1w3  = (const float*)d_in[9];
    const float* c1wo  = (const float*)d_in[10];
    const float* c2w1  = (const float*)d_in[11];
    const float* c2w2  = (const float*)d_in[12];
    const float* c2w3  = (const float*)d_in[13];
    const float* c2wo  = (const float*)d_in[14];
    const float* lin_w = (const float*)d_in[15];
    const float* lin_b = (const float*)d_in[16];
    const float* bn_g  = (const float*)d_in[17];
    const float* bn_b  = (const float*)d_in[18];
    float* out = (float*)d_out;

    init_kernel<<<(Bb*Nn*8 + 255)/256, 256>>>(Z, emb);
    build_edges<<<(Bb*Nn*Nn + 255)/256, 256>>>(xyz);
    radial_kernel<<<2664, 160>>>(c0w1, c0w2, c0w3, c0wo,
                                 c1w1, c1w2, c1w3, c1wo,
                                 c2w1, c2w2, c2w3, c2wo);
    scatter_kernel<0><<<296, 256>>>();
    scatter_kernel<1><<<296, 256>>>();
    scatter_kernel<2><<<296, 256>>>();
    final_kernel<<<1, 64>>>(lin_w, lin_b, bn_g, bn_b, out);
}

// round 8
// speedup vs baseline: 1.0150x; 1.0150x over previous
#include <cuda_runtime.h>
#include <cuda_bf16.h>
#include <math.h>

#define Bb 2
#define Nn 286
#define HH 150
#define TE 16           // edges per tile
#define MAXE 82944      // >= B*N*(N+1)/2 = 82082

typedef unsigned long long ULL;

// ---------------- device scratch (no allocations allowed) ----------------
// NOTE: these symbols must ONLY be referenced from device code (host binding
// of a __device__ symbol silently reads the host shadow via ATS on GB300).
__device__ int   g_edge_count;
__device__ int   g_packed[MAXE];  // (b<<20)|(i<<10)|j
__device__ float g_dist[MAXE];
__device__ float g_f0[Bb*Nn*4];
__device__ float g_f1[Bb*Nn*8];
__device__ float g_f2[Bb*Nn*8];
__device__ float g_f3[Bb*Nn*8];
__device__ float g_K0[MAXE*32];
__device__ float g_K1[MAXE*64];
__device__ float g_K2[MAXE*64];

__device__ __forceinline__ float sp_act(float x) {
    float t = 5.0f * x;
    if (t > 15.0f) return x;
    return 0.2f * __logf(1.0f + __expf(t));
}

// ---- packed fp32x2 FMA helpers (bit-exact 2x FFMA) ----
__device__ __forceinline__ void ffma2(ULL &d, ULL a, ULL b) {
    asm("fma.rn.f32x2 %0, %1, %2, %0;" : "+l"(d) : "l"(a), "l"(b));
}
__device__ __forceinline__ ULL bcast2(float w) {
    ULL r; asm("mov.b64 %0, {%1, %1};" : "=l"(r) : "f"(w)); return r;
}
__device__ __forceinline__ float2 unpk(ULL a) {
    float lo, hi; asm("mov.b64 {%0, %1}, %2;" : "=f"(lo), "=f"(hi) : "l"(a));
    return make_float2(lo, hi);
}

// ---------------- init kernels (split so radial is the 6th launch) --------
__global__ void zero1_kernel() {
    int t = blockIdx.x * blockDim.x + threadIdx.x;
    if (t == 0) g_edge_count = 0;
    if (t < Bb*Nn*8) g_f1[t] = 0.f;
}
__global__ void zero2_kernel() {
    int t = blockIdx.x * blockDim.x + threadIdx.x;
    if (t < Bb*Nn*8) g_f2[t] = 0.f;
}
__global__ void zero3_kernel() {
    int t = blockIdx.x * blockDim.x + threadIdx.x;
    if (t < Bb*Nn*8) g_f3[t] = 0.f;
}
__global__ void embed_kernel(const int* __restrict__ Z, const float* __restrict__ emb) {
    int t = blockIdx.x * blockDim.x + threadIdx.x;
    if (t < Bb*Nn*4) {
        int n = t >> 2, c = t & 3;
        g_f0[t] = emb[Z[n]*4 + c];
    }
}

// ---------------- build compacted unordered-pair list ----------------
__global__ void build_edges(const float* __restrict__ xyz) {
    int t = blockIdx.x * blockDim.x + threadIdx.x;
    if (t >= Bb*Nn*Nn) return;
    int b = t / (Nn*Nn);
    int r = t % (Nn*Nn);
    int i = r / Nn, j = r % Nn;
    if (j < i) return;
    const float* pi = xyz + (b*Nn + i)*3;
    const float* pj = xyz + (b*Nn + j)*3;
    float dx = pi[0]-pj[0], dy = pi[1]-pj[1], dz = pi[2]-pj[2];
    float d = sqrtf(dx*dx + dy*dy + dz*dz + 1e-12f);
    if (d <= 3.0f) {
        int idx = atomicAdd(&g_edge_count, 1);
        g_packed[idx] = (b << 20) | (i << 10) | j;
        g_dist[idx]   = d;
    }
}

// -------- hidden 150x150 layer over a 16-edge tile (f32x2, prefetch) ------
__device__ __forceinline__ void hidden_layer(const float* __restrict__ src,
                                             float* __restrict__ dst,
                                             const float* __restrict__ W, int tid) {
    if (tid >= HH) return;
    ULL acc[8];
    #pragma unroll
    for (int q = 0; q < 8; q++) acc[q] = 0ULL;
    const float* wc = W + tid;
    float wA[6], wB[6];
    #pragma unroll
    for (int u = 0; u < 6; u++) wA[u] = __ldg(wc + u*HH);
    #pragma unroll 1
    for (int kk = 0; kk < HH; kk += 6) {
        if (kk + 6 < HH) {
            #pragma unroll
            for (int u = 0; u < 6; u++) wB[u] = __ldg(wc + (kk + 6 + u)*HH);
        }
        #pragma unroll
        for (int u = 0; u < 6; u++) {
            ULL wd = bcast2(wA[u]);
            const ulonglong2* hr = reinterpret_cast<const ulonglong2*>(src + (kk + u)*TE);
            ulonglong2 p0 = hr[0], p1 = hr[1], p2 = hr[2], p3 = hr[3];
            ffma2(acc[0], p0.x, wd); ffma2(acc[1], p0.y, wd);
            ffma2(acc[2], p1.x, wd); ffma2(acc[3], p1.y, wd);
            ffma2(acc[4], p2.x, wd); ffma2(acc[5], p2.y, wd);
            ffma2(acc[6], p3.x, wd); ffma2(acc[7], p3.y, wd);
        }
        #pragma unroll
        for (int u = 0; u < 6; u++) wA[u] = wB[u];
    }
    const float S = 0.0816496580927726f;   // 1/sqrt(150)
    float4* dr = reinterpret_cast<float4*>(dst + tid*TE);
    #pragma unroll
    for (int q = 0; q < 4; q++) {
        float2 a = unpk(acc[2*q]), b = unpk(acc[2*q+1]);
        float4 o;
        o.x = sp_act(a.x*S); o.y = sp_act(a.y*S);
        o.z = sp_act(b.x*S); o.w = sp_act(b.y*S);
        dr[q] = o;
    }
}

// -------- output layer: 150 -> DIO per edge (f32x2, prefetch) -------------
template<int DIO>
__device__ __forceinline__ void out_layer(const float* __restrict__ HA,
                                          const float* __restrict__ wo,
                                          float* __restrict__ Kout, int tid) {
    constexpr int GROUPS = 128 / DIO;       // 4 (DIO=32) or 2 (DIO=64)
    constexpr int EPG    = TE / GROUPS;     // 4 or 8
    constexpr int NP     = EPG / 2;         // 2 or 4 packed accumulators
    if (tid >= 128) return;
    int o  = tid % DIO;
    int eg = tid / DIO;
    ULL acc[NP];
    #pragma unroll
    for (int q = 0; q < NP; q++) acc[q] = 0ULL;
    const float* wc = wo + o;
    float wA[6], wB[6];
    #pragma unroll
    for (int u = 0; u < 6; u++) wA[u] = __ldg(wc + u*DIO);
    #pragma unroll 1
    for (int kk = 0; kk < HH; kk += 6) {
        if (kk + 6 < HH) {
            #pragma unroll
            for (int u = 0; u < 6; u++) wB[u] = __ldg(wc + (kk + 6 + u)*DIO);
        }
        #pragma unroll
        for (int u = 0; u < 6; u++) {
            ULL wd = bcast2(wA[u]);
            const ULL* hr = reinterpret_cast<const ULL*>(HA + (kk + u)*TE + eg*EPG);
            #pragma unroll
            for (int q = 0; q < NP; q++) ffma2(acc[q], hr[q], wd);
        }
        #pragma unroll
        for (int u = 0; u < 6; u++) wA[u] = wB[u];
    }
    #pragma unroll
    for (int q = 0; q < NP; q++) {
        float2 v = unpk(acc[q]);
        Kout[(eg*EPG + 2*q    )*DIO + o] = v.x;
        Kout[(eg*EPG + 2*q + 1)*DIO + o] = v.y;
    }
}

// ---------------- radial MLP for all 3 convs (independent work items) ------
__global__ __launch_bounds__(160)
void radial_kernel(const float* __restrict__ c0w1, const float* __restrict__ c0w2,
                   const float* __restrict__ c0w3, const float* __restrict__ c0wo,
                   const float* __restrict__ c1w1, const float* __restrict__ c1w2,
                   const float* __restrict__ c1w3, const float* __restrict__ c1wo,
                   const float* __restrict__ c2w1, const float* __restrict__ c2w2,
                   const float* __restrict__ c2w3, const float* __restrict__ c2wo) {
    __shared__ __align__(16) float HA[HH*TE];
    __shared__ __align__(16) float HB[HH*TE];
    __shared__ float sb0[TE], sb1[TE], sb2[TE];

    const int tid = threadIdx.x;
    const int cnt = g_edge_count;
    const int ntiles = (cnt + TE - 1) / TE;
    const int total = 3 * ntiles;
    const float INV_SQRT3 = 0.5773502691896258f;
    const float PI_2 = 1.5707963267948966f;

    for (int work = blockIdx.x; work < total; work += gridDim.x) {
        int layer = work % 3;
        int tile  = work / 3;
        const float *w1, *w2, *w3, *wo;
        if (layer == 0)      { w1 = c0w1; w2 = c0w2; w3 = c0w3; wo = c0wo; }
        else if (layer == 1) { w1 = c1w1; w2 = c1w2; w3 = c1w3; wo = c1wo; }
        else                 { w1 = c2w1; w2 = c2w2; w3 = c2w3; wo = c2wo; }

        if (tid < TE) {
            int idx = tile*TE + tid;
            float d = (idx < cnt) ? g_dist[idx] : 1e9f;
            float x0 = d * (1.0f/1.5f);
            float x1 = x0 - 1.0f;
            float x2 = x0 - 2.0f;
            float c0 = cosf(PI_2*x0), c1 = cosf(PI_2*x1), c2 = cosf(PI_2*x2);
            sb0[tid] = (fabsf(x0) < 1.f) ? c0*c0 : 0.f;
            sb1[tid] = (fabsf(x1) < 1.f) ? c1*c1 : 0.f;
            sb2[tid] = (fabsf(x2) < 1.f) ? c2*c2 : 0.f;
        }
        __syncthreads();

        // layer 1: basis(3) -> 150
        if (tid < HH) {
            float wa = w1[tid]        * INV_SQRT3;
            float wb = w1[HH + tid]   * INV_SQRT3;
            float wc = w1[2*HH + tid] * INV_SQRT3;
            #pragma unroll
            for (int e = 0; e < TE; e++)
                HA[tid*TE + e] = sp_act(fmaf(sb0[e], wa, fmaf(sb1[e], wb, sb2[e]*wc)));
        }
        __syncthreads();
        hidden_layer(HA, HB, w2, tid);
        __syncthreads();
        hidden_layer(HB, HA, w3, tid);
        __syncthreads();

        if (layer == 0)      out_layer<32>(HA, wo, g_K0 + tile*TE*32, tid);
        else if (layer == 1) out_layer<64>(HA, wo, g_K1 + tile*TE*64, tid);
        else                 out_layer<64>(HA, wo, g_K2 + tile*TE*64, tid);
        __syncthreads();
    }
}

// ---------------- scatter: out[b,i] += K(e) @ f[b,j] (both directions) -----
template<int LAYER>
__global__ void scatter_kernel() {
    constexpr int DIN  = (LAYER == 0) ? 4 : 8;
    constexpr int DOUT = 8;
    const float* __restrict__ K   = (LAYER == 0) ? g_K0 : (LAYER == 1 ? g_K1 : g_K2);
    const float* __restrict__ fin = (LAYER == 0) ? g_f0 : (LAYER == 1 ? g_f1 : g_f2);
    float*       __restrict__ fout= (LAYER == 0) ? g_f1 : (LAYER == 1 ? g_f2 : g_f3);

    const int cnt = g_edge_count;
    const int total = cnt * DOUT;
    const float scale = rsqrtf(150.0f * (float)DIN);
    for (int t = blockIdx.x*blockDim.x + threadIdx.x; t < total;
         t += gridDim.x*blockDim.x) {
        int e = t / DOUT, a = t % DOUT;
        int p = g_packed[e];
        int b = p >> 20, i = (p >> 10) & 1023, j = p & 1023;
        const float* krow = K + e*(DIN*DOUT) + a*DIN;
        const float* fj = fin + (b*Nn + j)*DIN;
        const float* fi = fin + (b*Nn + i)*DIN;
        float s1 = 0.f, s2 = 0.f;
        #pragma unroll
        for (int ji = 0; ji < DIN; ji++) {
            float w = krow[ji];
            s1 = fmaf(w, fj[ji], s1);
            s2 = fmaf(w, fi[ji], s2);
        }
        atomicAdd(&fout[(b*Nn + i)*DOUT + a], s1 * scale);
        if (i != j) atomicAdd(&fout[(b*Nn + j)*DOUT + a], s2 * scale);
    }
}

// ---------------- epilogue: lp-pool, linear, batchnorm, leaky relu ----------
__global__ void final_kernel(const float* __restrict__ lin_w, const float* __restrict__ lin_b,
                             const float* __restrict__ bn_g,  const float* __restrict__ bn_b,
                             float* __restrict__ out) {
    __shared__ float pooled[2][24];
    __shared__ float yv[2][24];
    int t = threadIdx.x;
    if (t < 48) {
        int b = t / 24, c = t % 24;
        const float* src; int cc;
        if      (c < 8)  { src = g_f1; cc = c;      }
        else if (c < 16) { src = g_f2; cc = c - 8;  }
        else             { src = g_f3; cc = c - 16; }
        float s = 0.f;
        for (int n = 0; n < Nn; n++) {
            float v = src[(b*Nn + n)*8 + cc];
            s = fmaf(v, v, s);
        }
        pooled[b][c] = sqrtf(s + 1e-12f);
    }
    __syncthreads();
    if (t < 48) {
        int b = t / 24, o = t % 24;
        float s = lin_b[o];
        for (int c = 0; c < 24; c++) s = fmaf(pooled[b][c], lin_w[o*24 + c], s);
        yv[b][o] = s;
    }
    __syncthreads();
    if (t < 24) {
        float y0 = yv[0][t], y1 = yv[1][t];
        float m   = 0.5f * (y0 + y1);
        float d0  = y0 - m, d1 = y1 - m;
        float var = 0.5f * (d0*d0 + d1*d1);
        float inv = 1.0f / sqrtf(var + 1e-5f);
        #pragma unroll
        for (int b = 0; b < 2; b++) {
            float v = (yv[b][t] - m) * inv * bn_g[t] + bn_b[t];
            out[b*24 + t] = (v > 0.f) ? v : 0.2f * v;
        }
    }
}

// ---------------- launch (radial is the 6th launch -> ncu profiles it) -----
extern "C" void kernel_launch(void* const* d_in, const int* in_sizes, int n_in,
                              void* d_out, int out_size) {
    const float* xyz   = (const float*)d_in[0];
    const int*   Z     = (const int*)  d_in[1];
    const float* emb   = (const float*)d_in[2];
    const float* c0w1  = (const float*)d_in[3];
    const float* c0w2  = (const float*)d_in[4];
    const float* c0w3  = (const float*)d_in[5];
    const float* c0wo  = (const float*)d_in[6];
    const float* c1w1  = (const float*)d_in[7];
    const float* c1w2  = (const float*)d_in[8];
    const float* c1w3  = (const float*)d_in[9];
    const float* c1wo  = (const float*)d_in[10];
    const float* c2w1  = (const float*)d_in[11];
    const float* c2w2  = (const float*)d_in[12];
    const float* c2w3  = (const float*)d_in[13];
    const float* c2wo  = (const float*)d_in[14];
    const float* lin_w = (const float*)d_in[15];
    const float* lin_b = (const float*)d_in[16];
    const float* bn_g  = (const float*)d_in[17];
    const float* bn_b  = (const float*)d_in[18];
    float* out = (float*)d_out;

    zero1_kernel<<<18, 256>>>();
    zero2_kernel<<<18, 256>>>();
    zero3_kernel<<<18, 256>>>();
    embed_kernel<<<(Bb*Nn*4 + 255)/256, 256>>>(Z, emb);
    build_edges<<<(Bb*Nn*Nn + 255)/256, 256>>>(xyz);
    radial_kernel<<<1332, 160>>>(c0w1, c0w2, c0w3, c0wo,
                                 c1w1, c1w2, c1w3, c1wo,
                                 c2w1, c2w2, c2w3, c2wo);
    scatter_kernel<0><<<296, 256>>>();
    scatter_kernel<1><<<296, 256>>>();
    scatter_kernel<2><<<296, 256>>>();
    final_kernel<<<1, 64>>>(lin_w, lin_b, bn_g, bn_b, out);
}

// round 9
// speedup vs baseline: 1.0324x; 1.0171x over previous
#include <cuda_runtime.h>
#include <cuda_bf16.h>
#include <math.h>

#define Bb 2
#define Nn 286
#define HH 150
#define TE 16           // edges per tile
#define MAXE 82944      // >= B*N*(N+1)/2 = 82082

typedef unsigned long long ULL;

// ---------------- device scratch (no allocations allowed) ----------------
// NOTE: only reference these from device code (host binding of a __device__
// symbol silently reads the host shadow via ATS on GB300).
__device__ int   g_edge_count;
__device__ int   g_packed[MAXE];  // (b<<20)|(i<<10)|j
__device__ float g_dist[MAXE];
__device__ float g_f0[Bb*Nn*4];
__device__ float g_f1[Bb*Nn*8];
__device__ float g_f2[Bb*Nn*8];
__device__ float g_f3[Bb*Nn*8];
__device__ float g_K0[MAXE*32];
__device__ float g_K1[MAXE*64];
__device__ float g_K2[MAXE*64];

__device__ __forceinline__ float sp_act(float x) {
    float t = 5.0f * x;
    if (t > 15.0f) return x;
    return 0.2f * __logf(1.0f + __expf(t));
}

// ---- packed fp32x2 FMA helpers (bit-exact 2x FFMA) ----
__device__ __forceinline__ void ffma2(ULL &d, ULL a, ULL b) {
    asm("fma.rn.f32x2 %0, %1, %2, %0;" : "+l"(d) : "l"(a), "l"(b));
}
__device__ __forceinline__ ULL bcast2(float w) {
    ULL r; asm("mov.b64 %0, {%1, %1};" : "=l"(r) : "f"(w)); return r;
}
__device__ __forceinline__ float2 unpk(ULL a) {
    float lo, hi; asm("mov.b64 {%0, %1}, %2;" : "=f"(lo), "=f"(hi) : "l"(a));
    return make_float2(lo, hi);
}

// ---------------- init kernels ----------------
__global__ void zero_kernel() {
    int t = blockIdx.x * blockDim.x + threadIdx.x;
    if (t == 0) g_edge_count = 0;
    if (t < Bb*Nn*8) { g_f1[t] = 0.f; g_f2[t] = 0.f; g_f3[t] = 0.f; }
}
__global__ void embed_kernel(const int* __restrict__ Z, const float* __restrict__ emb) {
    int t = blockIdx.x * blockDim.x + threadIdx.x;
    if (t < Bb*Nn*4) {
        int n = t >> 2, c = t & 3;
        g_f0[t] = emb[Z[n]*4 + c];
    }
}

// ---------------- build compacted unordered-pair list ----------------
__global__ void build_edges(const float* __restrict__ xyz) {
    int t = blockIdx.x * blockDim.x + threadIdx.x;
    if (t >= Bb*Nn*Nn) return;
    int b = t / (Nn*Nn);
    int r = t % (Nn*Nn);
    int i = r / Nn, j = r % Nn;
    if (j < i) return;
    const float* pi = xyz + (b*Nn + i)*3;
    const float* pj = xyz + (b*Nn + j)*3;
    float dx = pi[0]-pj[0], dy = pi[1]-pj[1], dz = pi[2]-pj[2];
    float d = sqrtf(dx*dx + dy*dy + dz*dz + 1e-12f);
    if (d <= 3.0f) {
        int idx = atomicAdd(&g_edge_count, 1);
        g_packed[idx] = (b << 20) | (i << 10) | j;
        g_dist[idx]   = d;
    }
}

// ---- hidden 150x150 layer, 16-edge tile, 2 units/thread (3 warps) --------
// warps 0-1 (tid 0..63): units {tid, tid+86}; warp 2 (tid 64..95): unit tid (<86)
__device__ __forceinline__ void store_row(float* __restrict__ dst, int row,
                                          const ULL* acc) {
    const float S = 0.0816496580927726f;   // 1/sqrt(150)
    float4* dr = reinterpret_cast<float4*>(dst + row*TE);
    #pragma unroll
    for (int q = 0; q < 4; q++) {
        float2 a = unpk(acc[2*q]), b = unpk(acc[2*q+1]);
        float4 o;
        o.x = sp_act(a.x*S); o.y = sp_act(a.y*S);
        o.z = sp_act(b.x*S); o.w = sp_act(b.y*S);
        dr[q] = o;
    }
}

__device__ __forceinline__ void hidden_layer(const float* __restrict__ src,
                                             float* __restrict__ dst,
                                             const float* __restrict__ W, int tid) {
    if (tid < 64) {
        ULL a0[8], a1[8];
        #pragma unroll
        for (int q = 0; q < 8; q++) { a0[q] = 0ULL; a1[q] = 0ULL; }
        const float* wc0 = W + tid;
        const float* wc1 = W + tid + 86;
        #pragma unroll 1
        for (int kk = 0; kk < HH; kk += 6) {
            float w0[6], w1[6];
            #pragma unroll
            for (int u = 0; u < 6; u++) {
                w0[u] = __ldg(wc0 + (kk + u)*HH);
                w1[u] = __ldg(wc1 + (kk + u)*HH);
            }
            #pragma unroll
            for (int u = 0; u < 6; u++) {
                ULL d0 = bcast2(w0[u]), d1 = bcast2(w1[u]);
                const ulonglong2* hr = reinterpret_cast<const ulonglong2*>(src + (kk + u)*TE);
                ulonglong2 p0 = hr[0], p1 = hr[1], p2 = hr[2], p3 = hr[3];
                ffma2(a0[0], p0.x, d0); ffma2(a0[1], p0.y, d0);
                ffma2(a0[2], p1.x, d0); ffma2(a0[3], p1.y, d0);
                ffma2(a0[4], p2.x, d0); ffma2(a0[5], p2.y, d0);
                ffma2(a0[6], p3.x, d0); ffma2(a0[7], p3.y, d0);
                ffma2(a1[0], p0.x, d1); ffma2(a1[1], p0.y, d1);
                ffma2(a1[2], p1.x, d1); ffma2(a1[3], p1.y, d1);
                ffma2(a1[4], p2.x, d1); ffma2(a1[5], p2.y, d1);
                ffma2(a1[6], p3.x, d1); ffma2(a1[7], p3.y, d1);
            }
        }
        store_row(dst, tid, a0);
        store_row(dst, tid + 86, a1);
    } else if (tid < 86) {       // warp 2, lanes 64..85 active
        ULL a0[8];
        #pragma unroll
        for (int q = 0; q < 8; q++) a0[q] = 0ULL;
        const float* wc0 = W + tid;
        #pragma unroll 1
        for (int kk = 0; kk < HH; kk += 6) {
            float w0[6];
            #pragma unroll
            for (int u = 0; u < 6; u++) w0[u] = __ldg(wc0 + (kk + u)*HH);
            #pragma unroll
            for (int u = 0; u < 6; u++) {
                ULL d0 = bcast2(w0[u]);
                const ulonglong2* hr = reinterpret_cast<const ulonglong2*>(src + (kk + u)*TE);
                ulonglong2 p0 = hr[0], p1 = hr[1], p2 = hr[2], p3 = hr[3];
                ffma2(a0[0], p0.x, d0); ffma2(a0[1], p0.y, d0);
                ffma2(a0[2], p1.x, d0); ffma2(a0[3], p1.y, d0);
                ffma2(a0[4], p2.x, d0); ffma2(a0[5], p2.y, d0);
                ffma2(a0[6], p3.x, d0); ffma2(a0[7], p3.y, d0);
            }
        }
        store_row(dst, tid, a0);
    }
}

// ---- output layer: 150 -> DIO per edge, 64 threads, 16 edges/thread ------
template<int DIO>
__device__ __forceinline__ void out_layer(const float* __restrict__ HA,
                                          const float* __restrict__ wo,
                                          float* __restrict__ Kout, int tid) {
    constexpr int GROUPS = 64 / DIO;        // 2 (DIO=32) or 1 (DIO=64)
    constexpr int EPG    = TE / GROUPS;     // 8 or 16
    constexpr int NP     = EPG / 2;         // 4 or 8
    if (tid >= 64) return;
    int o  = tid % DIO;
    int eg = tid / DIO;
    ULL acc[NP];
    #pragma unroll
    for (int q = 0; q < NP; q++) acc[q] = 0ULL;
    const float* wc = wo + o;
    #pragma unroll 1
    for (int kk = 0; kk < HH; kk += 6) {
        float w[6];
        #pragma unroll
        for (int u = 0; u < 6; u++) w[u] = __ldg(wc + (kk + u)*DIO);
        #pragma unroll
        for (int u = 0; u < 6; u++) {
            ULL wd = bcast2(w[u]);
            const ulonglong2* hr =
                reinterpret_cast<const ulonglong2*>(HA + (kk + u)*TE + eg*EPG);
            #pragma unroll
            for (int q = 0; q < NP/2; q++) {
                ulonglong2 p = hr[q];
                ffma2(acc[2*q],   p.x, wd);
                ffma2(acc[2*q+1], p.y, wd);
            }
        }
    }
    #pragma unroll
    for (int q = 0; q < NP; q++) {
        float2 v = unpk(acc[q]);
        Kout[(eg*EPG + 2*q    )*DIO + o] = v.x;
        Kout[(eg*EPG + 2*q + 1)*DIO + o] = v.y;
    }
}

// ---------------- radial MLP for all 3 convs (independent work items) ------
__global__ __launch_bounds__(96)
void radial_kernel(const float* __restrict__ c0w1, const float* __restrict__ c0w2,
                   const float* __restrict__ c0w3, const float* __restrict__ c0wo,
                   const float* __restrict__ c1w1, const float* __restrict__ c1w2,
                   const float* __restrict__ c1w3, const float* __restrict__ c1wo,
                   const float* __restrict__ c2w1, const float* __restrict__ c2w2,
                   const float* __restrict__ c2w3, const float* __restrict__ c2wo) {
    __shared__ __align__(16) float HA[HH*TE];
    __shared__ __align__(16) float HB[HH*TE];
    __shared__ float sb0[TE], sb1[TE], sb2[TE];

    const int tid = threadIdx.x;
    const int cnt = g_edge_count;
    const int ntiles = (cnt + TE - 1) / TE;
    const int total = 3 * ntiles;
    const float INV_SQRT3 = 0.5773502691896258f;
    const float PI_2 = 1.5707963267948966f;

    for (int work = blockIdx.x; work < total; work += gridDim.x) {
        int layer = work % 3;
        int tile  = work / 3;
        const float *w1, *w2, *w3, *wo;
        if (layer == 0)      { w1 = c0w1; w2 = c0w2; w3 = c0w3; wo = c0wo; }
        else if (layer == 1) { w1 = c1w1; w2 = c1w2; w3 = c1w3; wo = c1wo; }
        else                 { w1 = c2w1; w2 = c2w2; w3 = c2w3; wo = c2wo; }

        if (tid < TE) {
            int idx = tile*TE + tid;
            float d = (idx < cnt) ? g_dist[idx] : 1e9f;
            float x0 = d * (1.0f/1.5f);
            float x1 = x0 - 1.0f;
            float x2 = x0 - 2.0f;
            float c0 = cosf(PI_2*x0), c1 = cosf(PI_2*x1), c2 = cosf(PI_2*x2);
            sb0[tid] = (fabsf(x0) < 1.f) ? c0*c0 : 0.f;
            sb1[tid] = (fabsf(x1) < 1.f) ? c1*c1 : 0.f;
            sb2[tid] = (fabsf(x2) < 1.f) ? c2*c2 : 0.f;
        }
        __syncthreads();

        // layer 1: basis(3) -> 150 (same unit mapping as hidden)
        {
            int u0 = tid, u1 = tid + 86;
            if (tid < 64) {
                float wa0 = w1[u0]*INV_SQRT3, wb0 = w1[HH+u0]*INV_SQRT3, wc0 = w1[2*HH+u0]*INV_SQRT3;
                float wa1 = w1[u1]*INV_SQRT3, wb1 = w1[HH+u1]*INV_SQRT3, wc1 = w1[2*HH+u1]*INV_SQRT3;
                #pragma unroll
                for (int e = 0; e < TE; e++) {
                    HA[u0*TE + e] = sp_act(fmaf(sb0[e], wa0, fmaf(sb1[e], wb0, sb2[e]*wc0)));
                    HA[u1*TE + e] = sp_act(fmaf(sb0[e], wa1, fmaf(sb1[e], wb1, sb2[e]*wc1)));
                }
            } else if (tid < 86) {
                float wa0 = w1[u0]*INV_SQRT3, wb0 = w1[HH+u0]*INV_SQRT3, wc0 = w1[2*HH+u0]*INV_SQRT3;
                #pragma unroll
                for (int e = 0; e < TE; e++)
                    HA[u0*TE + e] = sp_act(fmaf(sb0[e], wa0, fmaf(sb1[e], wb0, sb2[e]*wc0)));
            }
        }
        __syncthreads();
        hidden_layer(HA, HB, w2, tid);
        __syncthreads();
        hidden_layer(HB, HA, w3, tid);
        __syncthreads();

        if (layer == 0)      out_layer<32>(HA, wo, g_K0 + tile*TE*32, tid);
        else if (layer == 1) out_layer<64>(HA, wo, g_K1 + tile*TE*64, tid);
        else                 out_layer<64>(HA, wo, g_K2 + tile*TE*64, tid);
        __syncthreads();
    }
}

// ---------------- scatter: out[b,i] += K(e) @ f[b,j] (both directions) -----
template<int LAYER>
__global__ void scatter_kernel() {
    constexpr int DIN  = (LAYER == 0) ? 4 : 8;
    constexpr int DOUT = 8;
    const float* __restrict__ K   = (LAYER == 0) ? g_K0 : (LAYER == 1 ? g_K1 : g_K2);
    const float* __restrict__ fin = (LAYER == 0) ? g_f0 : (LAYER == 1 ? g_f1 : g_f2);
    float*       __restrict__ fout= (LAYER == 0) ? g_f1 : (LAYER == 1 ? g_f2 : g_f3);

    const int cnt = g_edge_count;
    const int total = cnt * DOUT;
    const float scale = rsqrtf(150.0f * (float)DIN);
    for (int t = blockIdx.x*blockDim.x + threadIdx.x; t < total;
         t += gridDim.x*blockDim.x) {
        int e = t / DOUT, a = t % DOUT;
        int p = g_packed[e];
        int b = p >> 20, i = (p >> 10) & 1023, j = p & 1023;
        const float* krow = K + e*(DIN*DOUT) + a*DIN;
        const float* fj = fin + (b*Nn + j)*DIN;
        const float* fi = fin + (b*Nn + i)*DIN;
        float s1 = 0.f, s2 = 0.f;
        #pragma unroll
        for (int ji = 0; ji < DIN; ji++) {
            float w = krow[ji];
            s1 = fmaf(w, fj[ji], s1);
            s2 = fmaf(w, fi[ji], s2);
        }
        atomicAdd(&fout[(b*Nn + i)*DOUT + a], s1 * scale);
        if (i != j) atomicAdd(&fout[(b*Nn + j)*DOUT + a], s2 * scale);
    }
}

// ---------------- epilogue: lp-pool, linear, batchnorm, leaky relu ----------
__global__ void final_kernel(const float* __restrict__ lin_w, const float* __restrict__ lin_b,
                             const float* __restrict__ bn_g,  const float* __restrict__ bn_b,
                             float* __restrict__ out) {
    __shared__ float pooled[2][24];
    __shared__ float yv[2][24];
    int t = threadIdx.x;
    if (t < 48) {
        int b = t / 24, c = t % 24;
        const float* src; int cc;
        if      (c < 8)  { src = g_f1; cc = c;      }
        else if (c < 16) { src = g_f2; cc = c - 8;  }
        else             { src = g_f3; cc = c - 16; }
        float s = 0.f;
        for (int n = 0; n < Nn; n++) {
            float v = src[(b*Nn + n)*8 + cc];
            s = fmaf(v, v, s);
        }
        pooled[b][c] = sqrtf(s + 1e-12f);
    }
    __syncthreads();
    if (t < 48) {
        int b = t / 24, o = t % 24;
        float s = lin_b[o];
        for (int c = 0; c < 24; c++) s = fmaf(pooled[b][c], lin_w[o*24 + c], s);
        yv[b][o] = s;
    }
    __syncthreads();
    if (t < 24) {
        float y0 = yv[0][t], y1 = yv[1][t];
        float m   = 0.5f * (y0 + y1);
        float d0  = y0 - m, d1 = y1 - m;
        float var = 0.5f * (d0*d0 + d1*d1);
        float inv = 1.0f / sqrtf(var + 1e-5f);
        #pragma unroll
        for (int b = 0; b < 2; b++) {
            float v = (yv[b][t] - m) * inv * bn_g[t] + bn_b[t];
            out[b*24 + t] = (v > 0.f) ? v : 0.2f * v;
        }
    }
}

// ---------------- launch (radial is 4th launch for ncu) --------------------
extern "C" void kernel_launch(void* const* d_in, const int* in_sizes, int n_in,
                              void* d_out, int out_size) {
    const float* xyz   = (const float*)d_in[0];
    const int*   Z     = (const int*)  d_in[1];
    const float* emb   = (const float*)d_in[2];
    const float* c0w1  = (const float*)d_in[3];
    const float* c0w2  = (const float*)d_in[4];
    const float* c0w3  = (const float*)d_in[5];
    const float* c0wo  = (const float*)d_in[6];
    const float* c1w1  = (const float*)d_in[7];
    const float* c1w2  = (const float*)d_in[8];
    const float* c1w3  = (const float*)d_in[9];
    const float* c1wo  = (const float*)d_in[10];
    const float* c2w1  = (const float*)d_in[11];
    const float* c2w2  = (const float*)d_in[12];
    const float* c2w3  = (const float*)d_in[13];
    const float* c2wo  = (const float*)d_in[14];
    const float* lin_w = (const float*)d_in[15];
    const float* lin_b = (const float*)d_in[16];
    const float* bn_g  = (const float*)d_in[17];
    const float* bn_b  = (const float*)d_in[18];
    float* out = (float*)d_out;

    zero_kernel<<<18, 256>>>();
    embed_kernel<<<(Bb*Nn*4 + 255)/256, 256>>>(Z, emb);
    build_edges<<<(Bb*Nn*Nn + 255)/256, 256>>>(xyz);
    radial_kernel<<<1332, 96>>>(c0w1, c0w2, c0w3, c0wo,
                                c1w1, c1w2, c1w3, c1wo,
                                c2w1, c2w2, c2w3, c2wo);
    scatter_kernel<0><<<296, 256>>>();
    scatter_kernel<1><<<296, 256>>>();
    scatter_kernel<2><<<296, 256>>>();
    final_kernel<<<1, 64>>>(lin_w, lin_b, bn_g, bn_b, out);
}

// round 10
// speedup vs baseline: 1.0688x; 1.0352x over previous
#include <cuda_runtime.h>
#include <cuda_bf16.h>
#include <math.h>

#define Bb 2
#define Nn 286
#define HH 150
#define TE 8            // edges per tile
#define MAXE 82944      // >= B*N*(N+1)/2 = 82082

typedef unsigned long long ULL;

// ---------------- device scratch (no allocations allowed) ----------------
// NOTE: only reference these from device code (host binding of a __device__
// symbol silently reads the host shadow via ATS on GB300).
__device__ int   g_edge_count;
__device__ int   g_packed[MAXE];  // (b<<20)|(i<<10)|j
__device__ float g_dist[MAXE];
__device__ float g_f0[Bb*Nn*4];
__device__ float g_f1[Bb*Nn*8];
__device__ float g_f2[Bb*Nn*8];
__device__ float g_f3[Bb*Nn*8];
__device__ float g_K0[MAXE*32];
__device__ float g_K1[MAXE*64];
__device__ float g_K2[MAXE*64];

__device__ __forceinline__ float sp_act(float x) {
    float t = 5.0f * x;
    if (t > 15.0f) return x;
    return 0.2f * __logf(1.0f + __expf(t));
}

// ---- packed fp32x2 FMA helpers (bit-exact 2x FFMA) ----
__device__ __forceinline__ void ffma2(ULL &d, ULL a, ULL b) {
    asm("fma.rn.f32x2 %0, %1, %2, %0;" : "+l"(d) : "l"(a), "l"(b));
}
__device__ __forceinline__ ULL bcast2(float w) {
    ULL r; asm("mov.b64 %0, {%1, %1};" : "=l"(r) : "f"(w)); return r;
}
__device__ __forceinline__ float2 unpk(ULL a) {
    float lo, hi; asm("mov.b64 {%0, %1}, %2;" : "=f"(lo), "=f"(hi) : "l"(a));
    return make_float2(lo, hi);
}

// ---------------- init kernels ----------------
__global__ void zero_kernel() {
    int t = blockIdx.x * blockDim.x + threadIdx.x;
    if (t == 0) g_edge_count = 0;
    if (t < Bb*Nn*8) { g_f1[t] = 0.f; g_f2[t] = 0.f; g_f3[t] = 0.f; }
}
__global__ void embed_kernel(const int* __restrict__ Z, const float* __restrict__ emb) {
    int t = blockIdx.x * blockDim.x + threadIdx.x;
    if (t < Bb*Nn*4) {
        int n = t >> 2, c = t & 3;
        g_f0[t] = emb[Z[n]*4 + c];
    }
}

// ---------------- build compacted unordered-pair list ----------------
__global__ void build_edges(const float* __restrict__ xyz) {
    int t = blockIdx.x * blockDim.x + threadIdx.x;
    if (t >= Bb*Nn*Nn) return;
    int b = t / (Nn*Nn);
    int r = t % (Nn*Nn);
    int i = r / Nn, j = r % Nn;
    if (j < i) return;
    const float* pi = xyz + (b*Nn + i)*3;
    const float* pj = xyz + (b*Nn + j)*3;
    float dx = pi[0]-pj[0], dy = pi[1]-pj[1], dz = pi[2]-pj[2];
    float d = sqrtf(dx*dx + dy*dy + dz*dz + 1e-12f);
    if (d <= 3.0f) {
        int idx = atomicAdd(&g_edge_count, 1);
        g_packed[idx] = (b << 20) | (i << 10) | j;
        g_dist[idx]   = d;
    }
}

// ---- hidden 150x150 layer, 8-edge tile, 2 units/thread (3 warps) ---------
// warps 0-1 (tid 0..63): units {tid, tid+86}; warp 2 (tid 64..95): unit tid (<86)
__device__ __forceinline__ void store_row(float* __restrict__ dst, int row,
                                          const ULL* acc) {
    const float S = 0.0816496580927726f;   // 1/sqrt(150)
    float4* dr = reinterpret_cast<float4*>(dst + row*TE);
    #pragma unroll
    for (int q = 0; q < 2; q++) {
        float2 a = unpk(acc[2*q]), b = unpk(acc[2*q+1]);
        float4 o;
        o.x = sp_act(a.x*S); o.y = sp_act(a.y*S);
        o.z = sp_act(b.x*S); o.w = sp_act(b.y*S);
        dr[q] = o;
    }
}

__device__ __forceinline__ void hidden_layer(const float* __restrict__ src,
                                             float* __restrict__ dst,
                                             const float* __restrict__ W, int tid) {
    if (tid < 64) {
        ULL a0[4], a1[4];
        #pragma unroll
        for (int q = 0; q < 4; q++) { a0[q] = 0ULL; a1[q] = 0ULL; }
        const float* wc0 = W + tid;
        const float* wc1 = W + tid + 86;
        #pragma unroll 1
        for (int kk = 0; kk < HH; kk += 6) {
            float w0[6], w1[6];
            #pragma unroll
            for (int u = 0; u < 6; u++) {
                w0[u] = __ldg(wc0 + (kk + u)*HH);
                w1[u] = __ldg(wc1 + (kk + u)*HH);
            }
            #pragma unroll
            for (int u = 0; u < 6; u++) {
                ULL d0 = bcast2(w0[u]), d1 = bcast2(w1[u]);
                const ulonglong2* hr = reinterpret_cast<const ulonglong2*>(src + (kk + u)*TE);
                ulonglong2 p0 = hr[0], p1 = hr[1];
                ffma2(a0[0], p0.x, d0); ffma2(a0[1], p0.y, d0);
                ffma2(a0[2], p1.x, d0); ffma2(a0[3], p1.y, d0);
                ffma2(a1[0], p0.x, d1); ffma2(a1[1], p0.y, d1);
                ffma2(a1[2], p1.x, d1); ffma2(a1[3], p1.y, d1);
            }
        }
        store_row(dst, tid, a0);
        store_row(dst, tid + 86, a1);
    } else if (tid < 86) {       // warp 2, lanes 64..85 active
        ULL a0[4];
        #pragma unroll
        for (int q = 0; q < 4; q++) a0[q] = 0ULL;
        const float* wc0 = W + tid;
        #pragma unroll 1
        for (int kk = 0; kk < HH; kk += 6) {
            float w0[6];
            #pragma unroll
            for (int u = 0; u < 6; u++) w0[u] = __ldg(wc0 + (kk + u)*HH);
            #pragma unroll
            for (int u = 0; u < 6; u++) {
                ULL d0 = bcast2(w0[u]);
                const ulonglong2* hr = reinterpret_cast<const ulonglong2*>(src + (kk + u)*TE);
                ulonglong2 p0 = hr[0], p1 = hr[1];
                ffma2(a0[0], p0.x, d0); ffma2(a0[1], p0.y, d0);
                ffma2(a0[2], p1.x, d0); ffma2(a0[3], p1.y, d0);
            }
        }
        store_row(dst, tid, a0);
    }
}

// ---- output layer: 150 -> DIO per edge, 64 threads, 8 edges spread -------
template<int DIO>
__device__ __forceinline__ void out_layer(const float* __restrict__ HA,
                                          const float* __restrict__ wo,
                                          float* __restrict__ Kout, int tid) {
    constexpr int GROUPS = 64 / DIO;        // 2 (DIO=32) or 1 (DIO=64)
    constexpr int EPG    = TE / GROUPS;     // 4 or 8
    constexpr int NP     = EPG / 2;         // 2 or 4
    if (tid >= 64) return;
    int o  = tid % DIO;
    int eg = tid / DIO;
    ULL acc[NP];
    #pragma unroll
    for (int q = 0; q < NP; q++) acc[q] = 0ULL;
    const float* wc = wo + o;
    #pragma unroll 1
    for (int kk = 0; kk < HH; kk += 6) {
        float w[6];
        #pragma unroll
        for (int u = 0; u < 6; u++) w[u] = __ldg(wc + (kk + u)*DIO);
        #pragma unroll
        for (int u = 0; u < 6; u++) {
            ULL wd = bcast2(w[u]);
            const ULL* hr = reinterpret_cast<const ULL*>(HA + (kk + u)*TE + eg*EPG);
            #pragma unroll
            for (int q = 0; q < NP; q++) ffma2(acc[q], hr[q], wd);
        }
    }
    #pragma unroll
    for (int q = 0; q < NP; q++) {
        float2 v = unpk(acc[q]);
        Kout[(eg*EPG + 2*q    )*DIO + o] = v.x;
        Kout[(eg*EPG + 2*q + 1)*DIO + o] = v.y;
    }
}

// ---------------- radial MLP for all 3 convs (independent work items) ------
__global__ __launch_bounds__(96, 14)
void radial_kernel(const float* __restrict__ c0w1, const float* __restrict__ c0w2,
                   const float* __restrict__ c0w3, const float* __restrict__ c0wo,
                   const float* __restrict__ c1w1, const float* __restrict__ c1w2,
                   const float* __restrict__ c1w3, const float* __restrict__ c1wo,
                   const float* __restrict__ c2w1, const float* __restrict__ c2w2,
                   const float* __restrict__ c2w3, const float* __restrict__ c2wo) {
    __shared__ __align__(16) float HA[HH*TE];
    __shared__ __align__(16) float HB[HH*TE];
    __shared__ float sb0[TE], sb1[TE], sb2[TE];

    const int tid = threadIdx.x;
    const int cnt = g_edge_count;
    const int ntiles = (cnt + TE - 1) / TE;
    const int total = 3 * ntiles;
    const float INV_SQRT3 = 0.5773502691896258f;
    const float PI_2 = 1.5707963267948966f;

    for (int work = blockIdx.x; work < total; work += gridDim.x) {
        int layer = work % 3;
        int tile  = work / 3;
        const float *w1, *w2, *w3, *wo;
        if (layer == 0)      { w1 = c0w1; w2 = c0w2; w3 = c0w3; wo = c0wo; }
        else if (layer == 1) { w1 = c1w1; w2 = c1w2; w3 = c1w3; wo = c1wo; }
        else                 { w1 = c2w1; w2 = c2w2; w3 = c2w3; wo = c2wo; }

        if (tid < TE) {
            int idx = tile*TE + tid;
            float d = (idx < cnt) ? g_dist[idx] : 1e9f;
            float x0 = d * (1.0f/1.5f);
            float x1 = x0 - 1.0f;
            float x2 = x0 - 2.0f;
            float c0 = cosf(PI_2*x0), c1 = cosf(PI_2*x1), c2 = cosf(PI_2*x2);
            sb0[tid] = (fabsf(x0) < 1.f) ? c0*c0 : 0.f;
            sb1[tid] = (fabsf(x1) < 1.f) ? c1*c1 : 0.f;
            sb2[tid] = (fabsf(x2) < 1.f) ? c2*c2 : 0.f;
        }
        __syncthreads();

        // layer 1: basis(3) -> 150 (same unit mapping as hidden)
        {
            int u0 = tid, u1 = tid + 86;
            if (tid < 64) {
                float wa0 = w1[u0]*INV_SQRT3, wb0 = w1[HH+u0]*INV_SQRT3, wc0 = w1[2*HH+u0]*INV_SQRT3;
                float wa1 = w1[u1]*INV_SQRT3, wb1 = w1[HH+u1]*INV_SQRT3, wc1 = w1[2*HH+u1]*INV_SQRT3;
                #pragma unroll
                for (int e = 0; e < TE; e++) {
                    HA[u0*TE + e] = sp_act(fmaf(sb0[e], wa0, fmaf(sb1[e], wb0, sb2[e]*wc0)));
                    HA[u1*TE + e] = sp_act(fmaf(sb0[e], wa1, fmaf(sb1[e], wb1, sb2[e]*wc1)));
                }
            } else if (tid < 86) {
                float wa0 = w1[u0]*INV_SQRT3, wb0 = w1[HH+u0]*INV_SQRT3, wc0 = w1[2*HH+u0]*INV_SQRT3;
                #pragma unroll
                for (int e = 0; e < TE; e++)
                    HA[u0*TE + e] = sp_act(fmaf(sb0[e], wa0, fmaf(sb1[e], wb0, sb2[e]*wc0)));
            }
        }
        __syncthreads();
        hidden_layer(HA, HB, w2, tid);
        __syncthreads();
        hidden_layer(HB, HA, w3, tid);
        __syncthreads();

        if (layer == 0)      out_layer<32>(HA, wo, g_K0 + tile*TE*32, tid);
        else if (layer == 1) out_layer<64>(HA, wo, g_K1 + tile*TE*64, tid);
        else                 out_layer<64>(HA, wo, g_K2 + tile*TE*64, tid);
        __syncthreads();
    }
}

// ---------------- scatter: out[b,i] += K(e) @ f[b,j] (both directions) -----
template<int LAYER>
__global__ void scatter_kernel() {
    constexpr int DIN  = (LAYER == 0) ? 4 : 8;
    constexpr int DOUT = 8;
    const float* __restrict__ K   = (LAYER == 0) ? g_K0 : (LAYER == 1 ? g_K1 : g_K2);
    const float* __restrict__ fin = (LAYER == 0) ? g_f0 : (LAYER == 1 ? g_f1 : g_f2);
    float*       __restrict__ fout= (LAYER == 0) ? g_f1 : (LAYER == 1 ? g_f2 : g_f3);

    const int cnt = g_edge_count;
    const int total = cnt * DOUT;
    const float scale = rsqrtf(150.0f * (float)DIN);
    for (int t = blockIdx.x*blockDim.x + threadIdx.x; t < total;
         t += gridDim.x*blockDim.x) {
        int e = t / DOUT, a = t % DOUT;
        int p = g_packed[e];
        int b = p >> 20, i = (p >> 10) & 1023, j = p & 1023;
        const float* krow = K + e*(DIN*DOUT) + a*DIN;
        const float* fj = fin + (b*Nn + j)*DIN;
        const float* fi = fin + (b*Nn + i)*DIN;
        float s1 = 0.f, s2 = 0.f;
        #pragma unroll
        for (int ji = 0; ji < DIN; ji++) {
            float w = krow[ji];
            s1 = fmaf(w, fj[ji], s1);
            s2 = fmaf(w, fi[ji], s2);
        }
        atomicAdd(&fout[(b*Nn + i)*DOUT + a], s1 * scale);
        if (i != j) atomicAdd(&fout[(b*Nn + j)*DOUT + a], s2 * scale);
    }
}

// ---------------- epilogue: lp-pool, linear, batchnorm, leaky relu ----------
__global__ void final_kernel(const float* __restrict__ lin_w, const float* __restrict__ lin_b,
                             const float* __restrict__ bn_g,  const float* __restrict__ bn_b,
                             float* __restrict__ out) {
    __shared__ float pooled[2][24];
    __shared__ float yv[2][24];
    int t = threadIdx.x;
    if (t < 48) {
        int b = t / 24, c = t % 24;
        const float* src; int cc;
        if      (c < 8)  { src = g_f1; cc = c;      }
        else if (c < 16) { src = g_f2; cc = c - 8;  }
        else             { src = g_f3; cc = c - 16; }
        float s = 0.f;
        for (int n = 0; n < Nn; n++) {
            float v = src[(b*Nn + n)*8 + cc];
            s = fmaf(v, v, s);
        }
        pooled[b][c] = sqrtf(s + 1e-12f);
    }
    __syncthreads();
    if (t < 48) {
        int b = t / 24, o = t % 24;
        float s = lin_b[o];
        for (int c = 0; c < 24; c++) s = fmaf(pooled[b][c], lin_w[o*24 + c], s);
        yv[b][o] = s;
    }
    __syncthreads();
    if (t < 24) {
        float y0 = yv[0][t], y1 = yv[1][t];
        float m   = 0.5f * (y0 + y1);
        float d0  = y0 - m, d1 = y1 - m;
        float var = 0.5f * (d0*d0 + d1*d1);
        float inv = 1.0f / sqrtf(var + 1e-5f);
        #pragma unroll
        for (int b = 0; b < 2; b++) {
            float v = (yv[b][t] - m) * inv * bn_g[t] + bn_b[t];
            out[b*24 + t] = (v > 0.f) ? v : 0.2f * v;
        }
    }
}

// ---------------- launch (radial is 4th launch for ncu) --------------------
extern "C" void kernel_launch(void* const* d_in, const int* in_sizes, int n_in,
                              void* d_out, int out_size) {
    const float* xyz   = (const float*)d_in[0];
    const int*   Z     = (const int*)  d_in[1];
    const float* emb   = (const float*)d_in[2];
    const float* c0w1  = (const float*)d_in[3];
    const float* c0w2  = (const float*)d_in[4];
    const float* c0w3  = (const float*)d_in[5];
    const float* c0wo  = (const float*)d_in[6];
    const float* c1w1  = (const float*)d_in[7];
    const float* c1w2  = (const float*)d_in[8];
    const float* c1w3  = (const float*)d_in[9];
    const float* c1wo  = (const float*)d_in[10];
    const float* c2w1  = (const float*)d_in[11];
    const float* c2w2  = (const float*)d_in[12];
    const float* c2w3  = (const float*)d_in[13];
    const float* c2wo  = (const float*)d_in[14];
    const float* lin_w = (const float*)d_in[15];
    const float* lin_b = (const float*)d_in[16];
    const float* bn_g  = (const float*)d_in[17];
    const float* bn_b  = (const float*)d_in[18];
    float* out = (float*)d_out;

    zero_kernel<<<18, 256>>>();
    embed_kernel<<<(Bb*Nn*4 + 255)/256, 256>>>(Z, emb);
    build_edges<<<(Bb*Nn*Nn + 255)/256, 256>>>(xyz);
    radial_kernel<<<2664, 96>>>(c0w1, c0w2, c0w3, c0wo,
                                c1w1, c1w2, c1w3, c1wo,
                                c2w1, c2w2, c2w3, c2wo);
    scatter_kernel<0><<<296, 256>>>();
    scatter_kernel<1><<<296, 256>>>();
    scatter_kernel<2><<<296, 256>>>();
    final_kernel<<<1, 64>>>(lin_w, lin_b, bn_g, bn_b, out);
}

// round 11
// speedup vs baseline: 1.0866x; 1.0167x over previous
#include <cuda_runtime.h>
#include <cuda_bf16.h>
#include <math.h>

#define Bb 2
#define Nn 286
#define HH 150
#define TE 8            // edges per tile
#define MAXE 82944      // >= B*N*(N+1)/2 = 82082
#define PART 888        // blocks per conv-layer partition

typedef unsigned long long ULL;

// ---------------- device scratch (no allocations allowed) ----------------
// NOTE: only reference these from device code (host binding of a __device__
// symbol silently reads the host shadow via ATS on GB300).
__device__ int   g_edge_count;
__device__ int   g_packed[MAXE];  // (b<<20)|(i<<10)|j
__device__ float g_dist[MAXE];
__device__ float g_f0[Bb*Nn*4];
__device__ float g_f1[Bb*Nn*8];
__device__ float g_f2[Bb*Nn*8];
__device__ float g_f3[Bb*Nn*8];
__device__ float g_K0[MAXE*32];
__device__ float g_K1[MAXE*64];
__device__ float g_K2[MAXE*64];

__device__ __forceinline__ float sp_act(float x) {
    float t = 5.0f * x;
    if (t > 15.0f) return x;
    return 0.2f * __logf(1.0f + __expf(t));
}

// ---- packed fp32x2 FMA helpers (bit-exact 2x FFMA) ----
__device__ __forceinline__ void ffma2(ULL &d, ULL a, ULL b) {
    asm("fma.rn.f32x2 %0, %1, %2, %0;" : "+l"(d) : "l"(a), "l"(b));
}
__device__ __forceinline__ ULL bcast2(float w) {
    ULL r; asm("mov.b64 %0, {%1, %1};" : "=l"(r) : "f"(w)); return r;
}
__device__ __forceinline__ float2 unpk(ULL a) {
    float lo, hi; asm("mov.b64 {%0, %1}, %2;" : "=f"(lo), "=f"(hi) : "l"(a));
    return make_float2(lo, hi);
}

// ---------------- init kernels ----------------
__global__ void zero_kernel() {
    int t = blockIdx.x * blockDim.x + threadIdx.x;
    if (t == 0) g_edge_count = 0;
    if (t < Bb*Nn*8) { g_f1[t] = 0.f; g_f2[t] = 0.f; g_f3[t] = 0.f; }
}
__global__ void embed_kernel(const int* __restrict__ Z, const float* __restrict__ emb) {
    int t = blockIdx.x * blockDim.x + threadIdx.x;
    if (t < Bb*Nn*4) {
        int n = t >> 2, c = t & 3;
        g_f0[t] = emb[Z[n]*4 + c];
    }
}

// ---------------- build compacted unordered-pair list ----------------
__global__ void build_edges(const float* __restrict__ xyz) {
    int t = blockIdx.x * blockDim.x + threadIdx.x;
    if (t >= Bb*Nn*Nn) return;
    int b = t / (Nn*Nn);
    int r = t % (Nn*Nn);
    int i = r / Nn, j = r % Nn;
    if (j < i) return;
    const float* pi = xyz + (b*Nn + i)*3;
    const float* pj = xyz + (b*Nn + j)*3;
    float dx = pi[0]-pj[0], dy = pi[1]-pj[1], dz = pi[2]-pj[2];
    float d = sqrtf(dx*dx + dy*dy + dz*dz + 1e-12f);
    if (d <= 3.0f) {
        int idx = atomicAdd(&g_edge_count, 1);
        g_packed[idx] = (b << 20) | (i << 10) | j;
        g_dist[idx]   = d;
    }
}

// ---- hidden 150x150 layer, 8-edge tile, 2 units/thread (3 warps) ---------
// warps 0-1 (tid 0..63): units {tid, tid+86}; warp 2 (tid 64..95): unit tid (<86)
__device__ __forceinline__ void store_row(float* __restrict__ dst, int row,
                                          const ULL* acc) {
    const float S = 0.0816496580927726f;   // 1/sqrt(150)
    float4* dr = reinterpret_cast<float4*>(dst + row*TE);
    #pragma unroll
    for (int q = 0; q < 2; q++) {
        float2 a = unpk(acc[2*q]), b = unpk(acc[2*q+1]);
        float4 o;
        o.x = sp_act(a.x*S); o.y = sp_act(a.y*S);
        o.z = sp_act(b.x*S); o.w = sp_act(b.y*S);
        dr[q] = o;
    }
}

__device__ __forceinline__ void hidden_layer(const float* __restrict__ src,
                                             float* __restrict__ dst,
                                             const float* __restrict__ W, int tid) {
    if (tid < 64) {
        ULL a0[4], a1[4];
        #pragma unroll
        for (int q = 0; q < 4; q++) { a0[q] = 0ULL; a1[q] = 0ULL; }
        const float* wc0 = W + tid;
        const float* wc1 = W + tid + 86;
        #pragma unroll 1
        for (int kk = 0; kk < HH; kk += 6) {
            float w0[6], w1[6];
            #pragma unroll
            for (int u = 0; u < 6; u++) {
                w0[u] = __ldg(wc0 + (kk + u)*HH);
                w1[u] = __ldg(wc1 + (kk + u)*HH);
            }
            #pragma unroll
            for (int u = 0; u < 6; u++) {
                ULL d0 = bcast2(w0[u]), d1 = bcast2(w1[u]);
                const ulonglong2* hr = reinterpret_cast<const ulonglong2*>(src + (kk + u)*TE);
                ulonglong2 p0 = hr[0], p1 = hr[1];
                ffma2(a0[0], p0.x, d0); ffma2(a0[1], p0.y, d0);
                ffma2(a0[2], p1.x, d0); ffma2(a0[3], p1.y, d0);
                ffma2(a1[0], p0.x, d1); ffma2(a1[1], p0.y, d1);
                ffma2(a1[2], p1.x, d1); ffma2(a1[3], p1.y, d1);
            }
        }
        store_row(dst, tid, a0);
        store_row(dst, tid + 86, a1);
    } else if (tid < 86) {       // warp 2, lanes 64..85 active
        ULL a0[4];
        #pragma unroll
        for (int q = 0; q < 4; q++) a0[q] = 0ULL;
        const float* wc0 = W + tid;
        #pragma unroll 1
        for (int kk = 0; kk < HH; kk += 6) {
            float w0[6];
            #pragma unroll
            for (int u = 0; u < 6; u++) w0[u] = __ldg(wc0 + (kk + u)*HH);
            #pragma unroll
            for (int u = 0; u < 6; u++) {
                ULL d0 = bcast2(w0[u]);
                const ulonglong2* hr = reinterpret_cast<const ulonglong2*>(src + (kk + u)*TE);
                ulonglong2 p0 = hr[0], p1 = hr[1];
                ffma2(a0[0], p0.x, d0); ffma2(a0[1], p0.y, d0);
                ffma2(a0[2], p1.x, d0); ffma2(a0[3], p1.y, d0);
            }
        }
        store_row(dst, tid, a0);
    }
}

// ---- output layer: 150 -> DIO per edge, 64 threads, 8 edges spread -------
template<int DIO>
__device__ __forceinline__ void out_layer(const float* __restrict__ HA,
                                          const float* __restrict__ wo,
                                          float* __restrict__ Kout, int tid) {
    constexpr int GROUPS = 64 / DIO;        // 2 (DIO=32) or 1 (DIO=64)
    constexpr int EPG    = TE / GROUPS;     // 4 or 8
    constexpr int NP     = EPG / 2;         // 2 or 4
    if (tid >= 64) return;
    int o  = tid % DIO;
    int eg = tid / DIO;
    ULL acc[NP];
    #pragma unroll
    for (int q = 0; q < NP; q++) acc[q] = 0ULL;
    const float* wc = wo + o;
    #pragma unroll 1
    for (int kk = 0; kk < HH; kk += 6) {
        float w[6];
        #pragma unroll
        for (int u = 0; u < 6; u++) w[u] = __ldg(wc + (kk + u)*DIO);
        #pragma unroll
        for (int u = 0; u < 6; u++) {
            ULL wd = bcast2(w[u]);
            const ULL* hr = reinterpret_cast<const ULL*>(HA + (kk + u)*TE + eg*EPG);
            #pragma unroll
            for (int q = 0; q < NP; q++) ffma2(acc[q], hr[q], wd);
        }
    }
    #pragma unroll
    for (int q = 0; q < NP; q++) {
        float2 v = unpk(acc[q]);
        Kout[(eg*EPG + 2*q    )*DIO + o] = v.x;
        Kout[(eg*EPG + 2*q + 1)*DIO + o] = v.y;
    }
}

// ---------------- radial MLP, layer-partitioned block mapping --------------
// Blocks [0,PART) -> conv0, [PART,2*PART) -> conv1, [2*PART,3*PART) -> conv2.
// Co-resident blocks on an SM share one conv's weights -> L1-resident (90KB).
__global__ __launch_bounds__(96, 14)
void radial_kernel(const float* __restrict__ c0w1, const float* __restrict__ c0w2,
                   const float* __restrict__ c0w3, const float* __restrict__ c0wo,
                   const float* __restrict__ c1w1, const float* __restrict__ c1w2,
                   const float* __restrict__ c1w3, const float* __restrict__ c1wo,
                   const float* __restrict__ c2w1, const float* __restrict__ c2w2,
                   const float* __restrict__ c2w3, const float* __restrict__ c2wo) {
    __shared__ __align__(16) float HA[HH*TE];
    __shared__ __align__(16) float HB[HH*TE];
    __shared__ float sb0[TE], sb1[TE], sb2[TE];

    const int tid = threadIdx.x;
    const int cnt = g_edge_count;
    const int ntiles = (cnt + TE - 1) / TE;
    const int layer = blockIdx.x / PART;
    const int tile0 = blockIdx.x % PART;
    const float INV_SQRT3 = 0.5773502691896258f;
    const float PI_2 = 1.5707963267948966f;

    const float *w1, *w2, *w3, *wo;
    if (layer == 0)      { w1 = c0w1; w2 = c0w2; w3 = c0w3; wo = c0wo; }
    else if (layer == 1) { w1 = c1w1; w2 = c1w2; w3 = c1w3; wo = c1wo; }
    else                 { w1 = c2w1; w2 = c2w2; w3 = c2w3; wo = c2wo; }

    for (int tile = tile0; tile < ntiles; tile += PART) {
        if (tid < TE) {
            int idx = tile*TE + tid;
            float d = (idx < cnt) ? g_dist[idx] : 1e9f;
            float x0 = d * (1.0f/1.5f);
            float x1 = x0 - 1.0f;
            float x2 = x0 - 2.0f;
            float c0 = cosf(PI_2*x0), c1 = cosf(PI_2*x1), c2 = cosf(PI_2*x2);
            sb0[tid] = (fabsf(x0) < 1.f) ? c0*c0 : 0.f;
            sb1[tid] = (fabsf(x1) < 1.f) ? c1*c1 : 0.f;
            sb2[tid] = (fabsf(x2) < 1.f) ? c2*c2 : 0.f;
        }
        __syncthreads();

        // layer 1: basis(3) -> 150 (same unit mapping as hidden)
        {
            int u0 = tid, u1 = tid + 86;
            if (tid < 64) {
                float wa0 = w1[u0]*INV_SQRT3, wb0 = w1[HH+u0]*INV_SQRT3, wc0 = w1[2*HH+u0]*INV_SQRT3;
                float wa1 = w1[u1]*INV_SQRT3, wb1 = w1[HH+u1]*INV_SQRT3, wc1 = w1[2*HH+u1]*INV_SQRT3;
                #pragma unroll
                for (int e = 0; e < TE; e++) {
                    HA[u0*TE + e] = sp_act(fmaf(sb0[e], wa0, fmaf(sb1[e], wb0, sb2[e]*wc0)));
                    HA[u1*TE + e] = sp_act(fmaf(sb0[e], wa1, fmaf(sb1[e], wb1, sb2[e]*wc1)));
                }
            } else if (tid < 86) {
                float wa0 = w1[u0]*INV_SQRT3, wb0 = w1[HH+u0]*INV_SQRT3, wc0 = w1[2*HH+u0]*INV_SQRT3;
                #pragma unroll
                for (int e = 0; e < TE; e++)
                    HA[u0*TE + e] = sp_act(fmaf(sb0[e], wa0, fmaf(sb1[e], wb0, sb2[e]*wc0)));
            }
        }
        __syncthreads();
        hidden_layer(HA, HB, w2, tid);
        __syncthreads();
        hidden_layer(HB, HA, w3, tid);
        __syncthreads();

        if (layer == 0)      out_layer<32>(HA, wo, g_K0 + tile*TE*32, tid);
        else if (layer == 1) out_layer<64>(HA, wo, g_K1 + tile*TE*64, tid);
        else                 out_layer<64>(HA, wo, g_K2 + tile*TE*64, tid);
        __syncthreads();
    }
}

// ---------------- scatter: out[b,i] += K(e) @ f[b,j] (both directions) -----
template<int LAYER>
__global__ void scatter_kernel() {
    constexpr int DIN  = (LAYER == 0) ? 4 : 8;
    constexpr int DOUT = 8;
    const float* __restrict__ K   = (LAYER == 0) ? g_K0 : (LAYER == 1 ? g_K1 : g_K2);
    const float* __restrict__ fin = (LAYER == 0) ? g_f0 : (LAYER == 1 ? g_f1 : g_f2);
    float*       __restrict__ fout= (LAYER == 0) ? g_f1 : (LAYER == 1 ? g_f2 : g_f3);

    const int cnt = g_edge_count;
    const int total = cnt * DOUT;
    const float scale = rsqrtf(150.0f * (float)DIN);
    for (int t = blockIdx.x*blockDim.x + threadIdx.x; t < total;
         t += gridDim.x*blockDim.x) {
        int e = t / DOUT, a = t % DOUT;
        int p = g_packed[e];
        int b = p >> 20, i = (p >> 10) & 1023, j = p & 1023;
        const float* krow = K + e*(DIN*DOUT) + a*DIN;
        const float* fj = fin + (b*Nn + j)*DIN;
        const float* fi = fin + (b*Nn + i)*DIN;
        float s1 = 0.f, s2 = 0.f;
        #pragma unroll
        for (int ji = 0; ji < DIN; ji++) {
            float w = krow[ji];
            s1 = fmaf(w, fj[ji], s1);
            s2 = fmaf(w, fi[ji], s2);
        }
        atomicAdd(&fout[(b*Nn + i)*DOUT + a], s1 * scale);
        if (i != j) atomicAdd(&fout[(b*Nn + j)*DOUT + a], s2 * scale);
    }
}

// ---------------- epilogue: lp-pool, linear, batchnorm, leaky relu ----------
__global__ void final_kernel(const float* __restrict__ lin_w, const float* __restrict__ lin_b,
                             const float* __restrict__ bn_g,  const float* __restrict__ bn_b,
                             float* __restrict__ out) {
    __shared__ float pooled[2][24];
    __shared__ float yv[2][24];
    int t = threadIdx.x;
    if (t < 48) {
        int b = t / 24, c = t % 24;
        const float* src; int cc;
        if      (c < 8)  { src = g_f1; cc = c;      }
        else if (c < 16) { src = g_f2; cc = c - 8;  }
        else             { src = g_f3; cc = c - 16; }
        float s = 0.f;
        for (int n = 0; n < Nn; n++) {
            float v = src[(b*Nn + n)*8 + cc];
            s = fmaf(v, v, s);
        }
        pooled[b][c] = sqrtf(s + 1e-12f);
    }
    __syncthreads();
    if (t < 48) {
        int b = t / 24, o = t % 24;
        float s = lin_b[o];
        for (int c = 0; c < 24; c++) s = fmaf(pooled[b][c], lin_w[o*24 + c], s);
        yv[b][o] = s;
    }
    __syncthreads();
    if (t < 24) {
        float y0 = yv[0][t], y1 = yv[1][t];
        float m   = 0.5f * (y0 + y1);
        float d0  = y0 - m, d1 = y1 - m;
        float var = 0.5f * (d0*d0 + d1*d1);
        float inv = 1.0f / sqrtf(var + 1e-5f);
        #pragma unroll
        for (int b = 0; b < 2; b++) {
            float v = (yv[b][t] - m) * inv * bn_g[t] + bn_b[t];
            out[b*24 + t] = (v > 0.f) ? v : 0.2f * v;
        }
    }
}

// ---------------- launch (radial is 4th launch for ncu) --------------------
extern "C" void kernel_launch(void* const* d_in, const int* in_sizes, int n_in,
                              void* d_out, int out_size) {
    const float* xyz   = (const float*)d_in[0];
    const int*   Z     = (const int*)  d_in[1];
    const float* emb   = (const float*)d_in[2];
    const float* c0w1  = (const float*)d_in[3];
    const float* c0w2  = (const float*)d_in[4];
    const float* c0w3  = (const float*)d_in[5];
    const float* c0wo  = (const float*)d_in[6];
    const float* c1w1  = (const float*)d_in[7];
    const float* c1w2  = (const float*)d_in[8];
    const float* c1w3  = (const float*)d_in[9];
    const float* c1wo  = (const float*)d_in[10];
    const float* c2w1  = (const float*)d_in[11];
    const float* c2w2  = (const float*)d_in[12];
    const float* c2w3  = (const float*)d_in[13];
    const float* c2wo  = (const float*)d_in[14];
    const float* lin_w = (const float*)d_in[15];
    const float* lin_b = (const float*)d_in[16];
    const float* bn_g  = (const float*)d_in[17];
    const float* bn_b  = (const float*)d_in[18];
    float* out = (float*)d_out;

    zero_kernel<<<18, 256>>>();
    embed_kernel<<<(Bb*Nn*4 + 255)/256, 256>>>(Z, emb);
    build_edges<<<(Bb*Nn*Nn + 255)/256, 256>>>(xyz);
    radial_kernel<<<3*PART, 96>>>(c0w1, c0w2, c0w3, c0wo,
                                  c1w1, c1w2, c1w3, c1wo,
                                  c2w1, c2w2, c2w3, c2wo);
    scatter_kernel<0><<<296, 256>>>();
    scatter_kernel<1><<<296, 256>>>();
    scatter_kernel<2><<<296, 256>>>();
    final_kernel<<<1, 64>>>(lin_w, lin_b, bn_g, bn_b, out);
}